// round 3
// baseline (speedup 1.0000x reference)
#include <cuda_runtime.h>

// ManualChebConv restructured:
//   out[b] = sum_k T_k(L) (x[b] W_k) + bias
// Stage 1: T2..T4 via Chebyshev recurrence on [512,512] matrices (T1 = L).
// Stage 2: U[k][m][b*8+fo] = sum_fi x[b,m,fi] * W[k,fi,fo]
// Stage 3: one GEMM  out^T[n, c] = U0[n,c] + sum_{j=0..3} sum_m T[j][n][m] * U[j+1][m][c]
//          with c = b*8+fo, epilogue writes d_out[b, n, fo] directly.

#define NN    512
#define BATCH 1024
#define FIN   16
#define FOUT  8
#define KCHEB 5
#define LDC   8192   // BATCH * FOUT

__device__ float g_T[4 * NN * NN];        // slots: T1, T2, T3, T4
__device__ float g_U[KCHEB * NN * LDC];   // [k][m][b*8+fo]

// ---------------------------------------------------------------------------
// Copy L into g_T slot 0 (T1 = L)
// ---------------------------------------------------------------------------
__global__ void copy_L_kernel(const float* __restrict__ L) {
    int i = blockIdx.x * blockDim.x + threadIdx.x;   // 65536 float4
    reinterpret_cast<float4*>(g_T)[i] = reinterpret_cast<const float4*>(L)[i];
}

// ---------------------------------------------------------------------------
// Chebyshev recurrence step: C = 2 * L @ B - D  (D = identity if prevSlot < 0)
// All matrices 512x512. 64x64x16 tiles, 256 threads, 4x4 per thread.
// ---------------------------------------------------------------------------
__global__ void __launch_bounds__(256) cheb_step_kernel(
    const float* __restrict__ L, int srcSlot, int prevSlot, int dstSlot)
{
    __shared__ float As[16][68];
    __shared__ float Bs[16][68];

    const float* Bm = g_T + (size_t)srcSlot * NN * NN;
    float*       C  = g_T + (size_t)dstSlot * NN * NN;

    int tid = threadIdx.x;
    int tx = tid & 15, ty = tid >> 4;
    int bx = blockIdx.x, by = blockIdx.y;

    float acc[4][4] = {};

    for (int p0 = 0; p0 < NN; p0 += 16) {
        // A tile: L[n][p], 64 rows x 16 cols, stored transposed
        {
            int row  = tid >> 2;              // 0..63
            int p    = p0 + (tid & 3) * 4;
            float4 a = *reinterpret_cast<const float4*>(&L[(size_t)(by * 64 + row) * NN + p]);
            int kk = (tid & 3) * 4;
            As[kk + 0][row] = a.x;
            As[kk + 1][row] = a.y;
            As[kk + 2][row] = a.z;
            As[kk + 3][row] = a.w;
        }
        // B tile: Bm[p][c], 16 rows x 64 cols
        {
            int r = tid >> 4;                 // 0..15
            int c = (tid & 15) * 4;
            float4 bv = *reinterpret_cast<const float4*>(
                &Bm[(size_t)(p0 + r) * NN + bx * 64 + c]);
            *reinterpret_cast<float4*>(&Bs[r][c]) = bv;
        }
        __syncthreads();

        #pragma unroll
        for (int kk = 0; kk < 16; kk++) {
            float ra[4], rb[4];
            #pragma unroll
            for (int i = 0; i < 4; i++) ra[i] = As[kk][ty * 4 + i];
            #pragma unroll
            for (int i = 0; i < 4; i++) rb[i] = Bs[kk][tx * 4 + i];
            #pragma unroll
            for (int i = 0; i < 4; i++)
                #pragma unroll
                for (int j = 0; j < 4; j++) acc[i][j] += ra[i] * rb[j];
        }
        __syncthreads();
    }

    const float* D = (prevSlot >= 0) ? (g_T + (size_t)prevSlot * NN * NN) : nullptr;
    #pragma unroll
    for (int i = 0; i < 4; i++) {
        int n = by * 64 + ty * 4 + i;
        #pragma unroll
        for (int j = 0; j < 4; j++) {
            int c = bx * 64 + tx * 4 + j;
            float d = D ? D[(size_t)n * NN + c] : (n == c ? 1.0f : 0.0f);
            C[(size_t)n * NN + c] = 2.0f * acc[i][j] - d;
        }
    }
}

// ---------------------------------------------------------------------------
// U[k][m][b*8+fo] = sum_fi x[b,m,fi] * W[k,fi,fo]
// One thread per (b, m); b fastest -> coalesced 1KB writes per warp per k,
// each thread reads its own contiguous 64B of x.
// ---------------------------------------------------------------------------
__global__ void __launch_bounds__(256) build_u_kernel(
    const float* __restrict__ x, const float* __restrict__ W)
{
    __shared__ float Ws[KCHEB * FIN * FOUT];   // 640 floats
    int tid = threadIdx.x;
    for (int i = tid; i < KCHEB * FIN * FOUT; i += 256) Ws[i] = W[i];
    __syncthreads();

    int g = blockIdx.x * 256 + tid;            // 0 .. B*N-1
    int b = g & (BATCH - 1);
    int m = g >> 10;

    float xv[16];
    const float4* xp = reinterpret_cast<const float4*>(x + ((size_t)b * NN + m) * FIN);
    #pragma unroll
    for (int q = 0; q < 4; q++) {
        float4 v = xp[q];
        xv[q * 4 + 0] = v.x; xv[q * 4 + 1] = v.y;
        xv[q * 4 + 2] = v.z; xv[q * 4 + 3] = v.w;
    }

    #pragma unroll
    for (int k = 0; k < KCHEB; k++) {
        float acc[8] = {0.f, 0.f, 0.f, 0.f, 0.f, 0.f, 0.f, 0.f};
        #pragma unroll
        for (int fi = 0; fi < 16; fi++) {
            float xf = xv[fi];
            #pragma unroll
            for (int fo = 0; fo < 8; fo++)
                acc[fo] += xf * Ws[(k * 16 + fi) * 8 + fo];
        }
        float* dst = g_U + (size_t)k * NN * LDC + (size_t)m * LDC + (size_t)b * 8;
        float4 o0 = {acc[0], acc[1], acc[2], acc[3]};
        float4 o1 = {acc[4], acc[5], acc[6], acc[7]};
        reinterpret_cast<float4*>(dst)[0] = o0;
        reinterpret_cast<float4*>(dst)[1] = o1;
    }
}

// ---------------------------------------------------------------------------
// Big fused GEMM:  [512 x 2048] @ [2048 x 8192]
//   A[n, p] = g_T[j][n][m]  (p = j*512 + m)
//   B[p, c] = g_U[j+1][m][c]
//   C = A@B + U0 + bias, scattered to out[b, n, fo]  (c = b*8 + fo)
// 128x128x16 tiles, 256 threads, 8x8 per thread.
// ---------------------------------------------------------------------------
__global__ void __launch_bounds__(256, 2) big_gemm_kernel(
    const float* __restrict__ bias, float* __restrict__ out)
{
    __shared__ float As[16][132];
    __shared__ float Bs[16][132];

    int tid = threadIdx.x;
    int tx = tid & 15, ty = tid >> 4;
    int bx = blockIdx.x;   // 0..63 column tiles
    int by = blockIdx.y;   // 0..3  row tiles

    float acc[8][8] = {};

    for (int p0 = 0; p0 < 4 * NN; p0 += 16) {
        int j  = p0 >> 9;
        int m0 = p0 & (NN - 1);

        // A tile: 128 rows x 16 cols of g_T[j]
        {
            int row  = tid >> 2;                 // 0..63 (+64 second half)
            int mcol = m0 + (tid & 3) * 4;
            int kk   = (tid & 3) * 4;
            #pragma unroll
            for (int h = 0; h < 2; h++) {
                int n = by * 128 + row + h * 64;
                float4 a = *reinterpret_cast<const float4*>(
                    &g_T[(size_t)j * NN * NN + (size_t)n * NN + mcol]);
                As[kk + 0][row + h * 64] = a.x;
                As[kk + 1][row + h * 64] = a.y;
                As[kk + 2][row + h * 64] = a.z;
                As[kk + 3][row + h * 64] = a.w;
            }
        }
        // B tile: 16 rows x 128 cols of g_U[j+1]
        {
            int r = tid >> 5;                    // 0..7 (+8 second half)
            int c = (tid & 31) * 4;
            const float* Bp = g_U + (size_t)(j + 1) * NN * LDC
                                  + (size_t)(m0 + r) * LDC + (size_t)bx * 128 + c;
            float4 b0 = *reinterpret_cast<const float4*>(Bp);
            float4 b1 = *reinterpret_cast<const float4*>(Bp + 8 * LDC);
            *reinterpret_cast<float4*>(&Bs[r][c])     = b0;
            *reinterpret_cast<float4*>(&Bs[r + 8][c]) = b1;
        }
        __syncthreads();

        #pragma unroll
        for (int kk = 0; kk < 16; kk++) {
            float ra[8], rb[8];
            #pragma unroll
            for (int i = 0; i < 8; i++) ra[i] = As[kk][ty * 8 + i];
            #pragma unroll
            for (int i = 0; i < 8; i++) rb[i] = Bs[kk][tx * 8 + i];
            #pragma unroll
            for (int i = 0; i < 8; i++)
                #pragma unroll
                for (int r2 = 0; r2 < 8; r2++)
                    acc[i][r2] += ra[i] * rb[r2];
        }
        __syncthreads();
    }

    // Epilogue: + U0 (identity Chebyshev term) + bias, scatter to [b, n, fo].
    float bb[8];
    #pragma unroll
    for (int i = 0; i < 8; i++) bb[i] = bias[i];

    int bidx = bx * 16 + tx;   // batch index = c >> 3 (constant per thread)
    #pragma unroll
    for (int i = 0; i < 8; i++) {
        int n = by * 128 + ty * 8 + i;
        const float* u0 = g_U + (size_t)n * LDC + (size_t)bidx * 8;
        float4 ua = reinterpret_cast<const float4*>(u0)[0];
        float4 ub = reinterpret_cast<const float4*>(u0)[1];
        float4 o0 = {acc[i][0] + ua.x + bb[0], acc[i][1] + ua.y + bb[1],
                     acc[i][2] + ua.z + bb[2], acc[i][3] + ua.w + bb[3]};
        float4 o1 = {acc[i][4] + ub.x + bb[4], acc[i][5] + ub.y + bb[5],
                     acc[i][6] + ub.z + bb[6], acc[i][7] + ub.w + bb[7]};
        float* op = out + (size_t)bidx * (NN * FOUT) + (size_t)n * FOUT;
        reinterpret_cast<float4*>(op)[0] = o0;
        reinterpret_cast<float4*>(op)[1] = o1;
    }
}

// ---------------------------------------------------------------------------
extern "C" void kernel_launch(void* const* d_in, const int* in_sizes, int n_in,
                              void* d_out, int out_size)
{
    const float* x = (const float*)d_in[0];  // [1024, 512, 16]
    const float* L = (const float*)d_in[1];  // [512, 512]
    const float* W = (const float*)d_in[2];  // [5, 16, 8]
    const float* b = (const float*)d_in[3];  // [8]
    float* out = (float*)d_out;              // [1024, 512, 8]

    copy_L_kernel<<<256, 256>>>(L);                       // T1 = L
    dim3 cgrid(8, 8);
    cheb_step_kernel<<<cgrid, 256>>>(L, 0, -1, 1);        // T2 = 2 L T1 - I
    cheb_step_kernel<<<cgrid, 256>>>(L, 1,  0, 2);        // T3 = 2 L T2 - T1
    cheb_step_kernel<<<cgrid, 256>>>(L, 2,  1, 3);        // T4 = 2 L T3 - T2

    build_u_kernel<<<2048, 256>>>(x, W);                  // U_k = x W_k

    big_gemm_kernel<<<dim3(64, 4), 256>>>(b, out);        // out = sum T_k U_k
}

// round 5
// speedup vs baseline: 2.1009x; 2.1009x over previous
#include <cuda_runtime.h>
#include <cuda_bf16.h>
#include <cstdint>

// ===========================================================================
// ManualChebConv:  out[b] = sum_{k=0..4} T_k(L) (x[b] W_k) + bias
//  1. cheb chain: T2..T4 fp32 SIMT (+ fused bf16 hi/lo A-operand emit)
//  2. build_u: U_k = x W_k -> K-major bf16 hi/lo B-operand; U0+bias in out-layout
//  3. HMMA bf16 split GEMM (3-term, K'=6144): out = A@B + U0b
//     (tcgen05 unavailable: harness PTX target is compute_103, no 'a' features)
// ===========================================================================

#define NN    512
#define BATCH 1024
#define FIN   16
#define FOUT  8
#define CDIM  8192           // BATCH * FOUT
#define K2    2048           // 4 * NN (stacked Chebyshev K)
#define NCHUNK 96            // 3 split terms * (2048/64)
#define STAGES 3
#define ACHUNK_BYTES 16384   // 128 rows * 128 B
#define BCHUNK_BYTES 16384   // 128 rows * 128 B
#define STAGE_BYTES  (ACHUNK_BYTES + BCHUNK_BYTES)
#define SMEM_TOTAL   (STAGES * STAGE_BYTES)

__device__ float         g_T[4 * NN * NN];          // T1..T4 fp32
__device__ __nv_bfloat16 g_Ahi[NN * K2];            // [n][k], k = j*512+m
__device__ __nv_bfloat16 g_Alo[NN * K2];
__device__ __nv_bfloat16 g_Bhi[(size_t)CDIM * K2];  // [c][k] (col-major k x c)
__device__ __nv_bfloat16 g_Blo[(size_t)CDIM * K2];
__device__ float         g_U0b[(size_t)BATCH * NN * FOUT]; // U0 + bias, [b][n][fo]

// ---------------------------------------------------------------------------
__device__ __forceinline__ uint32_t smem_u32(const void* p) {
    uint32_t a;
    asm("{ .reg .u64 t; cvta.to.shared.u64 t, %1; cvt.u32.u64 %0, t; }" : "=r"(a) : "l"(p));
    return a;
}
__device__ __forceinline__ uint32_t swz(uint32_t off) { return off ^ ((off >> 3) & 0x70); }

__device__ __forceinline__ void cp_async16(uint32_t dst, const void* src) {
    asm volatile("cp.async.cg.shared.global [%0], [%1], 16;\n" :: "r"(dst), "l"(src));
}
__device__ __forceinline__ void cp_commit() { asm volatile("cp.async.commit_group;\n" ::: "memory"); }
template <int N> __device__ __forceinline__ void cp_wait() {
    asm volatile("cp.async.wait_group %0;\n" :: "n"(N) : "memory");
}

__device__ __forceinline__ void ldm_x4(uint32_t& r0, uint32_t& r1, uint32_t& r2,
                                       uint32_t& r3, uint32_t addr) {
    asm volatile("ldmatrix.sync.aligned.m8n8.x4.shared.b16 {%0,%1,%2,%3}, [%4];"
                 : "=r"(r0), "=r"(r1), "=r"(r2), "=r"(r3) : "r"(addr));
}
__device__ __forceinline__ void mma_bf16(float* d, const uint32_t* a,
                                         const uint32_t* b) {
    asm volatile(
        "mma.sync.aligned.m16n8k16.row.col.f32.bf16.bf16.f32 "
        "{%0,%1,%2,%3}, {%4,%5,%6,%7}, {%8,%9}, {%0,%1,%2,%3};"
        : "+f"(d[0]), "+f"(d[1]), "+f"(d[2]), "+f"(d[3])
        : "r"(a[0]), "r"(a[1]), "r"(a[2]), "r"(a[3]), "r"(b[0]), "r"(b[1]));
}

// ---------------------------------------------------------------------------
// T1 = L (fp32 slot 0) + bf16 hi/lo into A region 0
// ---------------------------------------------------------------------------
__global__ void __launch_bounds__(256) copy_L_kernel(const float* __restrict__ L) {
    int idx = blockIdx.x * 256 + threadIdx.x;       // 262144
    int n = idx >> 9, m = idx & 511;
    float v = L[idx];
    g_T[idx] = v;
    __nv_bfloat16 hi = __float2bfloat16(v);
    __nv_bfloat16 lo = __float2bfloat16(v - __bfloat162float(hi));
    g_Ahi[(size_t)n * K2 + m] = hi;
    g_Alo[(size_t)n * K2 + m] = lo;
}

// ---------------------------------------------------------------------------
// Chebyshev step: C = 2 L @ T_src - D.  32x64 tiles, grid (8,16) = 128 CTAs.
// Epilogue also emits bf16 hi/lo into A region dstSlot.
// ---------------------------------------------------------------------------
__global__ void __launch_bounds__(256) cheb_step_kernel(
    const float* __restrict__ L, int srcSlot, int prevSlot, int dstSlot)
{
    __shared__ float As[16][36];
    __shared__ float Bs[16][68];

    const float* Bm = g_T + (size_t)srcSlot * NN * NN;
    float*       C  = g_T + (size_t)dstSlot * NN * NN;

    int tid = threadIdx.x;
    int tx = tid & 15, ty = tid >> 4;
    int bx = blockIdx.x, by = blockIdx.y;

    float acc[2][4] = {};

    for (int p0 = 0; p0 < NN; p0 += 16) {
        if (tid < 128) {
            int row = tid >> 2;                  // 0..31
            int k4  = (tid & 3) * 4;
            float4 a = *reinterpret_cast<const float4*>(
                &L[(size_t)(by * 32 + row) * NN + p0 + k4]);
            As[k4 + 0][row] = a.x; As[k4 + 1][row] = a.y;
            As[k4 + 2][row] = a.z; As[k4 + 3][row] = a.w;
        }
        {
            int r = tid >> 4;                    // 0..15
            int c = (tid & 15) * 4;
            float4 bv = *reinterpret_cast<const float4*>(
                &Bm[(size_t)(p0 + r) * NN + bx * 64 + c]);
            *reinterpret_cast<float4*>(&Bs[r][c]) = bv;
        }
        __syncthreads();
        #pragma unroll
        for (int kk = 0; kk < 16; kk++) {
            float ra[2], rb[4];
            ra[0] = As[kk][ty * 2 + 0]; ra[1] = As[kk][ty * 2 + 1];
            #pragma unroll
            for (int j = 0; j < 4; j++) rb[j] = Bs[kk][tx * 4 + j];
            #pragma unroll
            for (int i = 0; i < 2; i++)
                #pragma unroll
                for (int j = 0; j < 4; j++) acc[i][j] += ra[i] * rb[j];
        }
        __syncthreads();
    }

    const float* D = (prevSlot >= 0) ? (g_T + (size_t)prevSlot * NN * NN) : nullptr;
    #pragma unroll
    for (int i = 0; i < 2; i++) {
        int n = by * 32 + ty * 2 + i;
        #pragma unroll
        for (int j = 0; j < 4; j++) {
            int c = bx * 64 + tx * 4 + j;
            float d = D ? D[(size_t)n * NN + c] : (n == c ? 1.0f : 0.0f);
            float v = 2.0f * acc[i][j] - d;
            C[(size_t)n * NN + c] = v;
            __nv_bfloat16 hi = __float2bfloat16(v);
            __nv_bfloat16 lo = __float2bfloat16(v - __bfloat162float(hi));
            size_t ai = (size_t)n * K2 + (size_t)dstSlot * NN + c;
            g_Ahi[ai] = hi;
            g_Alo[ai] = lo;
        }
    }
}

// ---------------------------------------------------------------------------
// U_k = x W_k.  Emits:
//   k=0   -> g_U0b[b][m][fo] = U0 + bias  (fp32, out layout, no transpose)
//   k>=1  -> g_Bhi/g_Blo[c][(k-1)*512+m]  (bf16 K-major via smem transpose)
// Block: 4 batches x 64 nodes. Grid (256, 8).
// ---------------------------------------------------------------------------
__global__ void __launch_bounds__(256) build_u_kernel(
    const float* __restrict__ x, const float* __restrict__ W,
    const float* __restrict__ bias)
{
    __shared__ float Ws[5 * FIN * FOUT];       // 640
    __shared__ float ts[32][65];

    int tid = threadIdx.x;
    for (int i = tid; i < 5 * FIN * FOUT; i += 256) Ws[i] = W[i];
    __syncthreads();

    int bx = blockIdx.x;                       // batch group of 4
    int bym = blockIdx.y;                      // m-tile of 64
    int b_l = tid >> 6, m_l = tid & 63;
    int b = bx * 4 + b_l, m = bym * 64 + m_l;

    float xv[16];
    const float4* xp = reinterpret_cast<const float4*>(x + ((size_t)b * NN + m) * FIN);
    #pragma unroll
    for (int q = 0; q < 4; q++) {
        float4 v = xp[q];
        xv[q * 4 + 0] = v.x; xv[q * 4 + 1] = v.y;
        xv[q * 4 + 2] = v.z; xv[q * 4 + 3] = v.w;
    }

    int row = tid >> 3, seg = tid & 7;
    int c_out = bx * 32 + row;

    #pragma unroll
    for (int k = 0; k < 5; k++) {
        float acc[8] = {};
        #pragma unroll
        for (int fi = 0; fi < 16; fi++) {
            float xf = xv[fi];
            #pragma unroll
            for (int fo = 0; fo < 8; fo++)
                acc[fo] += xf * Ws[(k * 16 + fi) * 8 + fo];
        }

        if (k == 0) {
            // direct write in out layout, bias folded
            float* dst = g_U0b + ((size_t)b * NN + m) * FOUT;
            float4 o0 = {acc[0] + bias[0], acc[1] + bias[1],
                         acc[2] + bias[2], acc[3] + bias[3]};
            float4 o1 = {acc[4] + bias[4], acc[5] + bias[5],
                         acc[6] + bias[6], acc[7] + bias[7]};
            reinterpret_cast<float4*>(dst)[0] = o0;
            reinterpret_cast<float4*>(dst)[1] = o1;
            continue;
        }

        __syncthreads();
        #pragma unroll
        for (int fo = 0; fo < 8; fo++) ts[b_l * 8 + fo][m_l] = acc[fo];
        __syncthreads();

        float v[8];
        #pragma unroll
        for (int j = 0; j < 8; j++) v[j] = ts[row][seg * 8 + j];

        __nv_bfloat162 hi[4], lo[4];
        #pragma unroll
        for (int jj = 0; jj < 4; jj++) {
            __nv_bfloat16 h0 = __float2bfloat16(v[2 * jj]);
            __nv_bfloat16 h1 = __float2bfloat16(v[2 * jj + 1]);
            hi[jj] = __nv_bfloat162(h0, h1);
            lo[jj] = __nv_bfloat162(
                __float2bfloat16(v[2 * jj]     - __bfloat162float(h0)),
                __float2bfloat16(v[2 * jj + 1] - __bfloat162float(h1)));
        }
        size_t off = (size_t)c_out * K2 + (size_t)(k - 1) * NN + bym * 64 + seg * 8;
        *reinterpret_cast<uint4*>(&g_Bhi[off]) = *reinterpret_cast<uint4*>(hi);
        *reinterpret_cast<uint4*>(&g_Blo[off]) = *reinterpret_cast<uint4*>(lo);
    }
}

// ---------------------------------------------------------------------------
// HMMA GEMM: C[n=512][c=8192] over K' = 6144 (3 bf16 split terms).
// CTA 128x128, 8 warps (4x2), warp tile 32x64, m16n8k16.
// Grid (64, 4) = 256 CTAs, occupancy 2. Epilogue: + g_U0b -> out[b][n][fo].
// ---------------------------------------------------------------------------
__global__ void __launch_bounds__(256, 2) hmma_gemm_kernel(float* __restrict__ out)
{
    extern __shared__ char smem[];
    uint32_t sb = smem_u32(smem);
    int tid = threadIdx.x;
    int lane = tid & 31, w = tid >> 5;
    int bx = blockIdx.x;    // c-tile (128 wide), 0..63
    int by = blockIdx.y;    // n-tile (128 wide), 0..3

    auto load_stage = [&](int s, int i) {
        int t  = i >> 5;                 // 0: hi*hi, 1: hi*lo, 2: lo*hi
        int kk = (i & 31) * 64;
        const __nv_bfloat16* Asrc = (t == 2) ? g_Alo : g_Ahi;
        const __nv_bfloat16* Bsrc = (t == 1) ? g_Blo : g_Bhi;
        uint32_t sA = sb + s * STAGE_BYTES;
        uint32_t sB = sA + ACHUNK_BYTES;
        #pragma unroll
        for (int q = 0; q < 4; q++) {            // A: 128 rows x 128B
            int idx = q * 256 + tid;
            int row = idx >> 3, seg = idx & 7;
            const void* g = Asrc + (size_t)(by * 128 + row) * K2 + kk + seg * 8;
            cp_async16(sA + swz(row * 128 + seg * 16), g);
        }
        #pragma unroll
        for (int q = 0; q < 4; q++) {            // B: 128 rows x 128B
            int idx = q * 256 + tid;
            int row = idx >> 3, seg = idx & 7;
            const void* g = Bsrc + (size_t)(bx * 128 + row) * K2 + kk + seg * 8;
            cp_async16(sB + swz(row * 128 + seg * 16), g);
        }
        cp_commit();
    };

    #pragma unroll
    for (int s = 0; s < STAGES; s++) load_stage(s, s);

    int warp_n0 = (w >> 1) * 32;
    int warp_c0 = (w & 1) * 64;

    // ldmatrix per-lane addressing (within a stage, before swizzle):
    int rowA  = warp_n0 + (lane & 15);
    int halfA = lane >> 4;
    int rowB  = warp_c0 + ((lane >> 4) & 1) * 8 + (lane & 7);
    int kselB = (lane >> 3) & 1;

    float acc[2][8][4] = {};

    for (int i = 0; i < NCHUNK; i++) {
        int s = i % 3;
        int rem = NCHUNK - 1 - i;
        if (rem >= 2)      cp_wait<2>();
        else if (rem == 1) cp_wait<1>();
        else               cp_wait<0>();
        __syncthreads();

        uint32_t sA = sb + s * STAGE_BYTES;
        uint32_t sB = sA + ACHUNK_BYTES;

        #pragma unroll
        for (int kk = 0; kk < 4; kk++) {
            uint32_t a[2][4];
            #pragma unroll
            for (int m2 = 0; m2 < 2; m2++) {
                uint32_t addr = sA + swz((rowA + m2 * 16) * 128 + (kk * 2 + halfA) * 16);
                ldm_x4(a[m2][0], a[m2][1], a[m2][2], a[m2][3], addr);
            }
            #pragma unroll
            for (int cg = 0; cg < 4; cg++) {
                uint32_t b[4];
                uint32_t addr = sB + swz((rowB + cg * 16) * 128 + (kk * 2 + kselB) * 16);
                ldm_x4(b[0], b[1], b[2], b[3], addr);
                #pragma unroll
                for (int m2 = 0; m2 < 2; m2++) {
                    mma_bf16(acc[m2][2 * cg + 0], a[m2], b + 0);
                    mma_bf16(acc[m2][2 * cg + 1], a[m2], b + 2);
                }
            }
        }
        __syncthreads();
        if (i + STAGES < NCHUNK) load_stage(s, i + STAGES);
    }

    // Epilogue: + (U0 + bias), write out[b][n][fo]
    int tr = lane >> 2, tc2 = (lane & 3) * 2;   // tc2 = fo (c-tiles are 8-aligned)
    #pragma unroll
    for (int m2 = 0; m2 < 2; m2++) {
        #pragma unroll
        for (int ct = 0; ct < 8; ct++) {
            int c = bx * 128 + warp_c0 + ct * 8 + tc2;
            int b = c >> 3;
            int n0 = by * 128 + warp_n0 + m2 * 16 + tr;
            size_t o0 = ((size_t)b * NN + n0) * FOUT + tc2;
            size_t o1 = o0 + 8 * FOUT;          // n0 + 8
            float2 u0 = *reinterpret_cast<const float2*>(&g_U0b[o0]);
            float2 u1 = *reinterpret_cast<const float2*>(&g_U0b[o1]);
            float2 r0 = {acc[m2][ct][0] + u0.x, acc[m2][ct][1] + u0.y};
            float2 r1 = {acc[m2][ct][2] + u1.x, acc[m2][ct][3] + u1.y};
            *reinterpret_cast<float2*>(&out[o0]) = r0;
            *reinterpret_cast<float2*>(&out[o1]) = r1;
        }
    }
}

// ---------------------------------------------------------------------------
extern "C" void kernel_launch(void* const* d_in, const int* in_sizes, int n_in,
                              void* d_out, int out_size)
{
    const float* x = (const float*)d_in[0];  // [1024, 512, 16]
    const float* L = (const float*)d_in[1];  // [512, 512]
    const float* W = (const float*)d_in[2];  // [5, 16, 8]
    const float* b = (const float*)d_in[3];  // [8]
    float* out = (float*)d_out;              // [1024, 512, 8]

    cudaFuncSetAttribute(hmma_gemm_kernel,
                         cudaFuncAttributeMaxDynamicSharedMemorySize, SMEM_TOTAL);

    copy_L_kernel<<<1024, 256>>>(L);                     // T1 = L (+ A region 0)
    dim3 cgrid(8, 16);
    cheb_step_kernel<<<cgrid, 256>>>(L, 0, -1, 1);       // T2
    cheb_step_kernel<<<cgrid, 256>>>(L, 1,  0, 2);       // T3
    cheb_step_kernel<<<cgrid, 256>>>(L, 2,  1, 3);       // T4

    build_u_kernel<<<dim3(256, 8), 256>>>(x, W, b);      // U_k + U0b

    hmma_gemm_kernel<<<dim3(64, 4), 256, SMEM_TOTAL>>>(out);
}

// round 6
// speedup vs baseline: 2.7164x; 1.2929x over previous
#include <cuda_runtime.h>
#include <cuda_bf16.h>
#include <cstdint>

// ===========================================================================
// ManualChebConv:  out[b] = sum_{k=0..4} T_k(L) (x[b] W_k) + bias
//  1. copy_L: bf16 hi/lo of L into stacked A slot 0
//  2. cheb composition on HMMA (depth 2):
//       T2 = 2 L@L - I
//       [T3 | T4] = 2 T2 @ [T1 | T2] - [T1 | I]    (all T_k symmetric)
//  3. build_u: U_k = x W_k -> K-major bf16 hi/lo B; U0+bias in out layout
//  4. HMMA bf16 split GEMM (3-term, K'=6144): out = A@B + U0b
// ===========================================================================

#define NN    512
#define BATCH 1024
#define FIN   16
#define FOUT  8
#define CDIM  8192           // BATCH * FOUT
#define K2    2048           // 4 * NN (stacked Chebyshev K)
#define NCHUNK 96            // 3 split terms * (2048/64)
#define STAGES 3
#define ACHUNK_BYTES 16384   // 128 rows * 128 B
#define BCHUNK_BYTES 16384
#define STAGE_BYTES  (ACHUNK_BYTES + BCHUNK_BYTES)
#define SMEM_TOTAL   (STAGES * STAGE_BYTES)

#define CH_STAGE_BYTES 16384 // A 64x128B + B 64x128B
#define CH_STAGES 3
#define CH_NCHUNK 24         // 3 terms * (512/64)

__device__ __nv_bfloat16 g_Ahi[NN * K2];            // [n][k], k = slot*512+m
__device__ __nv_bfloat16 g_Alo[NN * K2];
__device__ __nv_bfloat16 g_Bhi[(size_t)CDIM * K2];  // [c][k] K-major
__device__ __nv_bfloat16 g_Blo[(size_t)CDIM * K2];
__device__ float         g_U0b[(size_t)BATCH * NN * FOUT]; // U0+bias, [b][n][fo]

// ---------------------------------------------------------------------------
__device__ __forceinline__ uint32_t smem_u32(const void* p) {
    uint32_t a;
    asm("{ .reg .u64 t; cvta.to.shared.u64 t, %1; cvt.u32.u64 %0, t; }" : "=r"(a) : "l"(p));
    return a;
}
__device__ __forceinline__ uint32_t swz(uint32_t off) { return off ^ ((off >> 3) & 0x70); }

__device__ __forceinline__ void cp_async16(uint32_t dst, const void* src) {
    asm volatile("cp.async.cg.shared.global [%0], [%1], 16;\n" :: "r"(dst), "l"(src));
}
__device__ __forceinline__ void cp_commit() { asm volatile("cp.async.commit_group;\n" ::: "memory"); }
template <int N> __device__ __forceinline__ void cp_wait() {
    asm volatile("cp.async.wait_group %0;\n" :: "n"(N) : "memory");
}

__device__ __forceinline__ void ldm_x4(uint32_t& r0, uint32_t& r1, uint32_t& r2,
                                       uint32_t& r3, uint32_t addr) {
    asm volatile("ldmatrix.sync.aligned.m8n8.x4.shared.b16 {%0,%1,%2,%3}, [%4];"
                 : "=r"(r0), "=r"(r1), "=r"(r2), "=r"(r3) : "r"(addr));
}
__device__ __forceinline__ void mma_bf16(float* d, const uint32_t* a,
                                         const uint32_t* b) {
    asm volatile(
        "mma.sync.aligned.m16n8k16.row.col.f32.bf16.bf16.f32 "
        "{%0,%1,%2,%3}, {%4,%5,%6,%7}, {%8,%9}, {%0,%1,%2,%3};"
        : "+f"(d[0]), "+f"(d[1]), "+f"(d[2]), "+f"(d[3])
        : "r"(a[0]), "r"(a[1]), "r"(a[2]), "r"(a[3]), "r"(b[0]), "r"(b[1]));
}

// ---------------------------------------------------------------------------
// bf16 hi/lo of L into A slot 0 (T1 = L)
// ---------------------------------------------------------------------------
__global__ void __launch_bounds__(256) copy_L_kernel(const float* __restrict__ L) {
    int idx = blockIdx.x * 256 + threadIdx.x;       // 262144
    int n = idx >> 9, m = idx & 511;
    float v = L[idx];
    __nv_bfloat16 hi = __float2bfloat16(v);
    __nv_bfloat16 lo = __float2bfloat16(v - __bfloat162float(hi));
    g_Ahi[(size_t)n * K2 + m] = hi;
    g_Alo[(size_t)n * K2 + m] = lo;
}

// ---------------------------------------------------------------------------
// Cheb HMMA GEMM:  out = 2 * (A_slot @ B_slot) - D  over K=512, split-3 bf16.
// 64x64 tiles, 128 threads (4 warps 2x2, warp 32x32).
// Output columns c in [0, width); for width=1024 the upper half uses
// bSlot1/outSlot1.  D = L (if dMode==1 && lower half) else identity.
// Writes bf16 hi/lo into stacked A array at outSlot.
// ---------------------------------------------------------------------------
__global__ void __launch_bounds__(128) cheb_mma_kernel(
    const float* __restrict__ L, int aSlot, int bSlot0, int bSlot1,
    int outSlot0, int outSlot1, int dMode)
{
    __shared__ char chsmem[CH_STAGES * CH_STAGE_BYTES];
    uint32_t sb = smem_u32(chsmem);
    int tid = threadIdx.x;
    int lane = tid & 31, w = tid >> 5;
    int bx = blockIdx.x;                 // c-tile (64 wide)
    int by = blockIdx.y;                 // n-tile (64 wide)

    int c0    = bx * 64;
    int half  = (c0 >= NN) ? 1 : 0;
    int bSlot = half ? bSlot1 : bSlot0;
    int outSlot = half ? outSlot1 : outSlot0;
    int ccolBase = c0 & (NN - 1);
    bool dIsL = (dMode == 1) && (half == 0);

    auto load_stage = [&](int s, int i) {
        int t  = i >> 3;                 // 0: hi@hi, 1: hi@lo, 2: lo@hi
        int kk = (i & 7) * 64;
        const __nv_bfloat16* Asrc = (t == 2) ? g_Alo : g_Ahi;
        const __nv_bfloat16* Bsrc = (t == 1) ? g_Alo : g_Ahi;
        uint32_t sA = sb + s * CH_STAGE_BYTES;
        uint32_t sB = sA + 8192;
        #pragma unroll
        for (int q = 0; q < 4; q++) {    // A: 64 rows x 128B
            int idx = q * 128 + tid;
            int row = idx >> 3, seg = idx & 7;
            const void* g = Asrc + (size_t)(by * 64 + row) * K2 + aSlot * NN + kk + seg * 8;
            cp_async16(sA + swz(row * 128 + seg * 16), g);
        }
        #pragma unroll
        for (int q = 0; q < 4; q++) {    // B: 64 rows (cols, symmetric) x 128B
            int idx = q * 128 + tid;
            int row = idx >> 3, seg = idx & 7;
            const void* g = Bsrc + (size_t)(ccolBase + row) * K2 + bSlot * NN + kk + seg * 8;
            cp_async16(sB + swz(row * 128 + seg * 16), g);
        }
        cp_commit();
    };

    #pragma unroll
    for (int s = 0; s < CH_STAGES; s++) load_stage(s, s);

    int warp_n0 = (w >> 1) * 32;
    int warp_c0 = (w & 1) * 32;
    int rowA  = warp_n0 + (lane & 15);
    int halfA = lane >> 4;
    int rowB  = warp_c0 + ((lane >> 4) & 1) * 8 + (lane & 7);
    int kselB = (lane >> 3) & 1;

    float acc[2][4][4] = {};

    for (int i = 0; i < CH_NCHUNK; i++) {
        int s = i % CH_STAGES;
        int rem = CH_NCHUNK - 1 - i;
        if (rem >= 2)      cp_wait<2>();
        else if (rem == 1) cp_wait<1>();
        else               cp_wait<0>();
        __syncthreads();

        uint32_t sA = sb + s * CH_STAGE_BYTES;
        uint32_t sB = sA + 8192;

        #pragma unroll
        for (int kk = 0; kk < 4; kk++) {
            uint32_t a[2][4];
            #pragma unroll
            for (int m2 = 0; m2 < 2; m2++) {
                uint32_t addr = sA + swz((rowA + m2 * 16) * 128 + (kk * 2 + halfA) * 16);
                ldm_x4(a[m2][0], a[m2][1], a[m2][2], a[m2][3], addr);
            }
            #pragma unroll
            for (int cg = 0; cg < 2; cg++) {
                uint32_t b[4];
                uint32_t addr = sB + swz((rowB + cg * 16) * 128 + (kk * 2 + kselB) * 16);
                ldm_x4(b[0], b[1], b[2], b[3], addr);
                #pragma unroll
                for (int m2 = 0; m2 < 2; m2++) {
                    mma_bf16(acc[m2][2 * cg + 0], a[m2], b + 0);
                    mma_bf16(acc[m2][2 * cg + 1], a[m2], b + 2);
                }
            }
        }
        __syncthreads();
        if (i + CH_STAGES < CH_NCHUNK) load_stage(s, i + CH_STAGES);
    }

    // Epilogue: v = 2*acc - D; emit bf16 hi/lo into stacked A array.
    int tr = lane >> 2, tc2 = (lane & 3) * 2;
    #pragma unroll
    for (int m2 = 0; m2 < 2; m2++) {
        #pragma unroll
        for (int cf = 0; cf < 4; cf++) {
            #pragma unroll
            for (int rr = 0; rr < 2; rr++) {
                int n  = by * 64 + warp_n0 + m2 * 16 + tr + rr * 8;
                int cc = ccolBase + warp_c0 + cf * 8 + tc2;
                float d0, d1;
                if (dIsL) {
                    d0 = L[(size_t)n * NN + cc];
                    d1 = L[(size_t)n * NN + cc + 1];
                } else {
                    d0 = (n == cc)     ? 1.0f : 0.0f;
                    d1 = (n == cc + 1) ? 1.0f : 0.0f;
                }
                float v0 = 2.0f * acc[m2][cf][rr * 2 + 0] - d0;
                float v1 = 2.0f * acc[m2][cf][rr * 2 + 1] - d1;
                __nv_bfloat16 h0 = __float2bfloat16(v0);
                __nv_bfloat16 h1 = __float2bfloat16(v1);
                __nv_bfloat162 hv(h0, h1);
                __nv_bfloat162 lv(__float2bfloat16(v0 - __bfloat162float(h0)),
                                  __float2bfloat16(v1 - __bfloat162float(h1)));
                size_t off = (size_t)n * K2 + outSlot * NN + cc;
                *reinterpret_cast<__nv_bfloat162*>(&g_Ahi[off]) = hv;
                *reinterpret_cast<__nv_bfloat162*>(&g_Alo[off]) = lv;
            }
        }
    }
}

// ---------------------------------------------------------------------------
// U_k = x W_k.  k=0 -> g_U0b (U0+bias, out layout); k>=1 -> bf16 hi/lo B.
// ---------------------------------------------------------------------------
__global__ void __launch_bounds__(256) build_u_kernel(
    const float* __restrict__ x, const float* __restrict__ W,
    const float* __restrict__ bias)
{
    __shared__ float Ws[5 * FIN * FOUT];
    __shared__ float ts[32][65];

    int tid = threadIdx.x;
    for (int i = tid; i < 5 * FIN * FOUT; i += 256) Ws[i] = W[i];
    __syncthreads();

    int bx = blockIdx.x;                       // batch group of 4
    int bym = blockIdx.y;                      // m-tile of 64
    int b_l = tid >> 6, m_l = tid & 63;
    int b = bx * 4 + b_l, m = bym * 64 + m_l;

    float xv[16];
    const float4* xp = reinterpret_cast<const float4*>(x + ((size_t)b * NN + m) * FIN);
    #pragma unroll
    for (int q = 0; q < 4; q++) {
        float4 v = xp[q];
        xv[q * 4 + 0] = v.x; xv[q * 4 + 1] = v.y;
        xv[q * 4 + 2] = v.z; xv[q * 4 + 3] = v.w;
    }

    int row = tid >> 3, seg = tid & 7;
    int c_out = bx * 32 + row;

    #pragma unroll
    for (int k = 0; k < 5; k++) {
        float acc[8] = {};
        #pragma unroll
        for (int fi = 0; fi < 16; fi++) {
            float xf = xv[fi];
            #pragma unroll
            for (int fo = 0; fo < 8; fo++)
                acc[fo] += xf * Ws[(k * 16 + fi) * 8 + fo];
        }

        if (k == 0) {
            float* dst = g_U0b + ((size_t)b * NN + m) * FOUT;
            float4 o0 = {acc[0] + bias[0], acc[1] + bias[1],
                         acc[2] + bias[2], acc[3] + bias[3]};
            float4 o1 = {acc[4] + bias[4], acc[5] + bias[5],
                         acc[6] + bias[6], acc[7] + bias[7]};
            reinterpret_cast<float4*>(dst)[0] = o0;
            reinterpret_cast<float4*>(dst)[1] = o1;
            continue;
        }

        __syncthreads();
        #pragma unroll
        for (int fo = 0; fo < 8; fo++) ts[b_l * 8 + fo][m_l] = acc[fo];
        __syncthreads();

        float v[8];
        #pragma unroll
        for (int j = 0; j < 8; j++) v[j] = ts[row][seg * 8 + j];

        __nv_bfloat162 hi[4], lo[4];
        #pragma unroll
        for (int jj = 0; jj < 4; jj++) {
            __nv_bfloat16 h0 = __float2bfloat16(v[2 * jj]);
            __nv_bfloat16 h1 = __float2bfloat16(v[2 * jj + 1]);
            hi[jj] = __nv_bfloat162(h0, h1);
            lo[jj] = __nv_bfloat162(
                __float2bfloat16(v[2 * jj]     - __bfloat162float(h0)),
                __float2bfloat16(v[2 * jj + 1] - __bfloat162float(h1)));
        }
        size_t off = (size_t)c_out * K2 + (size_t)(k - 1) * NN + bym * 64 + seg * 8;
        *reinterpret_cast<uint4*>(&g_Bhi[off]) = *reinterpret_cast<uint4*>(hi);
        *reinterpret_cast<uint4*>(&g_Blo[off]) = *reinterpret_cast<uint4*>(lo);
    }
}

// ---------------------------------------------------------------------------
// Main HMMA GEMM: C[n=512][c=8192] over K'=6144 (3 bf16 split terms).
// CTA 128x128, 8 warps (4x2), warp 32x64. Grid (64,4), occupancy 2.
// ---------------------------------------------------------------------------
__global__ void __launch_bounds__(256, 2) hmma_gemm_kernel(float* __restrict__ out)
{
    extern __shared__ char smem[];
    uint32_t sb = smem_u32(smem);
    int tid = threadIdx.x;
    int lane = tid & 31, w = tid >> 5;
    int bx = blockIdx.x;    // c-tile (128 wide)
    int by = blockIdx.y;    // n-tile (128 wide)

    auto load_stage = [&](int s, int i) {
        int t  = i >> 5;
        int kk = (i & 31) * 64;
        const __nv_bfloat16* Asrc = (t == 2) ? g_Alo : g_Ahi;
        const __nv_bfloat16* Bsrc = (t == 1) ? g_Blo : g_Bhi;
        uint32_t sA = sb + s * STAGE_BYTES;
        uint32_t sB = sA + ACHUNK_BYTES;
        #pragma unroll
        for (int q = 0; q < 4; q++) {
            int idx = q * 256 + tid;
            int row = idx >> 3, seg = idx & 7;
            const void* g = Asrc + (size_t)(by * 128 + row) * K2 + kk + seg * 8;
            cp_async16(sA + swz(row * 128 + seg * 16), g);
        }
        #pragma unroll
        for (int q = 0; q < 4; q++) {
            int idx = q * 256 + tid;
            int row = idx >> 3, seg = idx & 7;
            const void* g = Bsrc + (size_t)(bx * 128 + row) * K2 + kk + seg * 8;
            cp_async16(sB + swz(row * 128 + seg * 16), g);
        }
        cp_commit();
    };

    #pragma unroll
    for (int s = 0; s < STAGES; s++) load_stage(s, s);

    int warp_n0 = (w >> 1) * 32;
    int warp_c0 = (w & 1) * 64;
    int rowA  = warp_n0 + (lane & 15);
    int halfA = lane >> 4;
    int rowB  = warp_c0 + ((lane >> 4) & 1) * 8 + (lane & 7);
    int kselB = (lane >> 3) & 1;

    float acc[2][8][4] = {};

    for (int i = 0; i < NCHUNK; i++) {
        int s = i % 3;
        int rem = NCHUNK - 1 - i;
        if (rem >= 2)      cp_wait<2>();
        else if (rem == 1) cp_wait<1>();
        else               cp_wait<0>();
        __syncthreads();

        uint32_t sA = sb + s * STAGE_BYTES;
        uint32_t sB = sA + ACHUNK_BYTES;

        #pragma unroll
        for (int kk = 0; kk < 4; kk++) {
            uint32_t a[2][4];
            #pragma unroll
            for (int m2 = 0; m2 < 2; m2++) {
                uint32_t addr = sA + swz((rowA + m2 * 16) * 128 + (kk * 2 + halfA) * 16);
                ldm_x4(a[m2][0], a[m2][1], a[m2][2], a[m2][3], addr);
            }
            #pragma unroll
            for (int cg = 0; cg < 4; cg++) {
                uint32_t b[4];
                uint32_t addr = sB + swz((rowB + cg * 16) * 128 + (kk * 2 + kselB) * 16);
                ldm_x4(b[0], b[1], b[2], b[3], addr);
                #pragma unroll
                for (int m2 = 0; m2 < 2; m2++) {
                    mma_bf16(acc[m2][2 * cg + 0], a[m2], b + 0);
                    mma_bf16(acc[m2][2 * cg + 1], a[m2], b + 2);
                }
            }
        }
        __syncthreads();
        if (i + STAGES < NCHUNK) load_stage(s, i + STAGES);
    }

    // Epilogue: + (U0 + bias), write out[b][n][fo]
    int tr = lane >> 2, tc2 = (lane & 3) * 2;
    #pragma unroll
    for (int m2 = 0; m2 < 2; m2++) {
        #pragma unroll
        for (int ct = 0; ct < 8; ct++) {
            int c = bx * 128 + warp_c0 + ct * 8 + tc2;
            int b = c >> 3;
            int n0 = by * 128 + warp_n0 + m2 * 16 + tr;
            size_t o0 = ((size_t)b * NN + n0) * FOUT + tc2;
            size_t o1 = o0 + 8 * FOUT;
            float2 u0 = *reinterpret_cast<const float2*>(&g_U0b[o0]);
            float2 u1 = *reinterpret_cast<const float2*>(&g_U0b[o1]);
            float2 r0 = {acc[m2][ct][0] + u0.x, acc[m2][ct][1] + u0.y};
            float2 r1 = {acc[m2][ct][2] + u1.x, acc[m2][ct][3] + u1.y};
            *reinterpret_cast<float2*>(&out[o0]) = r0;
            *reinterpret_cast<float2*>(&out[o1]) = r1;
        }
    }
}

// ---------------------------------------------------------------------------
extern "C" void kernel_launch(void* const* d_in, const int* in_sizes, int n_in,
                              void* d_out, int out_size)
{
    const float* x = (const float*)d_in[0];  // [1024, 512, 16]
    const float* L = (const float*)d_in[1];  // [512, 512]
    const float* W = (const float*)d_in[2];  // [5, 16, 8]
    const float* b = (const float*)d_in[3];  // [8]
    float* out = (float*)d_out;              // [1024, 512, 8]

    cudaFuncSetAttribute(hmma_gemm_kernel,
                         cudaFuncAttributeMaxDynamicSharedMemorySize, SMEM_TOTAL);

    copy_L_kernel<<<1024, 256>>>(L);                       // T1 hi/lo

    // T2 = 2 L@L - I
    cheb_mma_kernel<<<dim3(8, 8), 128>>>(L, 0, 0, 0, 1, 1, 0);
    // [T3 | T4] = 2 T2 @ [T1 | T2] - [T1 | I]
    cheb_mma_kernel<<<dim3(16, 8), 128>>>(L, 1, 0, 1, 2, 3, 1);

    build_u_kernel<<<dim3(256, 8), 256>>>(x, W, b);        // U_k + U0b

    hmma_gemm_kernel<<<dim3(64, 4), 256, SMEM_TOTAL>>>(out);
}